// round 17
// baseline (speedup 1.0000x reference)
#include <cuda_runtime.h>

// Problem constants
#define TOK_TOTAL 4096      // B_SZ * L = 2 * 2048
#define Dm        1024
#define TPB       256
#define OUT_F4_PER_TOK 8196               // (2*1024+1)*16/4

// Proj kernel tiling: 32 tokens per block, staged in 4 groups of 8
#define PTILE     32
#define PGRP      8
#define NBLK_PROJ (TOK_TOTAL / PTILE)     // 128

// Expand kernel: 2 tokens per block
#define ETOKS     2
#define NBLK_EXP  (TOK_TOTAL / ETOKS)     // 2048

// Projection scratch: [4096][9] float4 = [4096][36] floats.
// Row: B = f4[0..3], C = f4[4..7], s_delta = f4[8].x
#define PROJ_F4   9
__device__ float4 g_proj4[TOK_TOTAL * PROJ_F4];

__device__ __forceinline__ float softplus_f(float v) {
    // matches jax.nn.softplus = max(x,0) + log1p(exp(-|x|))
    return fmaxf(v, 0.0f) + log1pf(__expf(-fabsf(v)));
}

// ---------------------------------------------------------------------------
// Kernel 1: projections, W-reuse tiled. 32 tokens/block in 4 groups of 8.
// W (132 KB) is pulled from L2 once per block and stays L1-resident across
// the 4 groups -> total W L2 traffic = 128 x 132 KB = 17 MB.
// ---------------------------------------------------------------------------
__global__ void __launch_bounds__(TPB) ssm_proj_kernel(
    const float* __restrict__ x,
    const float* __restrict__ Wb,
    const float* __restrict__ Wc,
    const float* __restrict__ Wd)
{
    __shared__ float4 sx[PGRP * Dm / 4];   // 32 KB: 8 x rows

    float* gp = (float*)g_proj4;

    const int tid  = threadIdx.x;
    const int bt   = blockIdx.x;
    const int lane = tid & 31;
    const int w    = tid >> 5;

    for (int g = 0; g < PTILE / PGRP; ++g) {
        const int tok0 = bt * PTILE + g * PGRP;

        // Stage 8 contiguous x rows (32 KB)
        const float4* x4 = (const float4*)x + (size_t)tok0 * (Dm / 4);
        #pragma unroll
        for (int i = 0; i < (PGRP * Dm / 4) / TPB; ++i)    // 8 iters
            sx[tid + i * TPB] = __ldg(x4 + tid + i * TPB);
        __syncthreads();

        // 33 dot products x 8 tokens. Warp w owns cols {w, w+8, ...}
        for (int c = w; c < 33; c += 8) {
            const float* Wrow = (c < 16) ? (Wb + c * Dm)
                              : (c < 32) ? (Wc + (c - 16) * Dm)
                              : Wd;
            const float4* W4 = (const float4*)Wrow;
            float acc[PGRP];
            #pragma unroll
            for (int t = 0; t < PGRP; ++t) acc[t] = 0.0f;
            #pragma unroll
            for (int k = 0; k < 8; ++k) {
                float4 wv = __ldg(W4 + lane + 32 * k);   // L1-resident across groups
                #pragma unroll
                for (int t = 0; t < PGRP; ++t) {
                    float4 xv = sx[t * 256 + lane + 32 * k];
                    acc[t] = fmaf(xv.x, wv.x, acc[t]);
                    acc[t] = fmaf(xv.y, wv.y, acc[t]);
                    acc[t] = fmaf(xv.z, wv.z, acc[t]);
                    acc[t] = fmaf(xv.w, wv.w, acc[t]);
                }
            }
            #pragma unroll
            for (int t = 0; t < PGRP; ++t) {
                float a = acc[t];
                a += __shfl_xor_sync(0xffffffffu, a, 16);
                a += __shfl_xor_sync(0xffffffffu, a, 8);
                a += __shfl_xor_sync(0xffffffffu, a, 4);
                a += __shfl_xor_sync(0xffffffffu, a, 2);
                a += __shfl_xor_sync(0xffffffffu, a, 1);
                if (lane == 0) gp[(size_t)(tok0 + t) * 36 + c] = a;
            }
        }
        __syncthreads();   // group done before sx is overwritten
    }
}

// ---------------------------------------------------------------------------
// Kernel 2: expansion. 2 tokens/block; A loaded once per j, 1/A shared.
// Pure streaming stores, zero projection work.
// ---------------------------------------------------------------------------
__global__ void __launch_bounds__(TPB, 5) ssm_expand_kernel(
    const float* __restrict__ x,
    const float* __restrict__ A,
    const float* __restrict__ dp,
    float* __restrict__ out)
{
    __shared__ float2 s_dx[ETOKS][Dm];    // 16 KB: (Delta, x) per (token, d)

    const int tid = threadIdx.x;
    const int bt  = blockIdx.x;
    const int tok0 = bt * ETOKS;

    const float4* A4 = (const float4*)A;
    const float*  gp = (const float*)g_proj4;

    float4 a_pre = __ldg(A4 + tid);       // warm A under staging

    // ---- Stage: softplus once per (token, d); pack (Delta, x) ----
    {
        const float4 dpv = __ldg((const float4*)dp + tid);
        const int d0 = tid * 4;
        #pragma unroll
        for (int t = 0; t < ETOKS; ++t) {
            const float  sdel = __ldg(gp + (size_t)(tok0 + t) * 36 + 32);
            const float4 xv   = __ldg((const float4*)x + (size_t)(tok0 + t) * (Dm / 4) + tid);
            s_dx[t][d0 + 0] = make_float2(softplus_f(sdel + dpv.x), xv.x);
            s_dx[t][d0 + 1] = make_float2(softplus_f(sdel + dpv.y), xv.y);
            s_dx[t][d0 + 2] = make_float2(softplus_f(sdel + dpv.z), xv.z);
            s_dx[t][d0 + 3] = make_float2(softplus_f(sdel + dpv.w), xv.w);
        }
    }
    __syncthreads();

    // Per-thread invariant B quads (4 distinct addresses/warp, L1/L2 cached)
    const float4 Bq0 = __ldg(&g_proj4[(size_t)(tok0 + 0) * PROJ_F4 + (tid & 3)]);
    const float4 Bq1 = __ldg(&g_proj4[(size_t)(tok0 + 1) * PROJ_F4 + (tid & 3)]);

    float4* out4 = (float4*)out;
    float4* ob0 = out4 + (size_t)(tok0 + 0) * OUT_F4_PER_TOK;
    float4* ob1 = out4 + (size_t)(tok0 + 1) * OUT_F4_PER_TOK;

    // ---- Hot loop: A loaded ONCE per j; 1/A shared across both tokens ----
    #pragma unroll 4
    for (int j = 0; j < 16; ++j) {
        const int f = tid + j * TPB;
        const int d = (tid >> 2) + j * 64;

        const float4 a = (j == 0) ? a_pre : __ldg(A4 + f);
        float4 ra;
        ra.x = __fdividef(1.0f, a.x);
        ra.y = __fdividef(1.0f, a.y);
        ra.z = __fdividef(1.0f, a.z);
        ra.w = __fdividef(1.0f, a.w);

        // --- token 0 ---
        {
            const float2 dx = s_dx[0][d];
            float4 ab;
            ab.x = __expf(dx.x * a.x);
            ab.y = __expf(dx.x * a.y);
            ab.z = __expf(dx.x * a.z);
            ab.w = __expf(dx.x * a.w);
            const float K0 = (Bq0.x * dx.y) * ra.x;
            const float K1 = (Bq0.y * dx.y) * ra.y;
            const float K2 = (Bq0.z * dx.y) * ra.z;
            const float K3 = (Bq0.w * dx.y) * ra.w;
            float4 o2;
            o2.x = fmaf(ab.x, K0, -K0);
            o2.y = fmaf(ab.y, K1, -K1);
            o2.z = fmaf(ab.z, K2, -K2);
            o2.w = fmaf(ab.w, K3, -K3);
            __stcs(ob0 + f, ab);
            __stcs(ob0 + 4096 + f, o2);
        }
        // --- token 1 ---
        {
            const float2 dx = s_dx[1][d];
            float4 ab;
            ab.x = __expf(dx.x * a.x);
            ab.y = __expf(dx.x * a.y);
            ab.z = __expf(dx.x * a.z);
            ab.w = __expf(dx.x * a.w);
            const float K0 = (Bq1.x * dx.y) * ra.x;
            const float K1 = (Bq1.y * dx.y) * ra.y;
            const float K2 = (Bq1.z * dx.y) * ra.z;
            const float K3 = (Bq1.w * dx.y) * ra.w;
            float4 o2;
            o2.x = fmaf(ab.x, K0, -K0);
            o2.y = fmaf(ab.y, K1, -K1);
            o2.z = fmaf(ab.z, K2, -K2);
            o2.w = fmaf(ab.w, K3, -K3);
            __stcs(ob1 + f, ab);
            __stcs(ob1 + 4096 + f, o2);
        }
    }

    // C rows: 16 floats at f4 offset 8192
    if (tid < 4) {
        __stcs(ob0 + 8192 + tid, __ldg(&g_proj4[(size_t)(tok0 + 0) * PROJ_F4 + 4 + tid]));
        __stcs(ob1 + 8192 + tid, __ldg(&g_proj4[(size_t)(tok0 + 1) * PROJ_F4 + 4 + tid]));
    }
}

extern "C" void kernel_launch(void* const* d_in, const int* in_sizes, int n_in,
                              void* d_out, int out_size)
{
    const float* x  = (const float*)d_in[0];
    const float* Wb = (const float*)d_in[1];
    const float* Wc = (const float*)d_in[2];
    const float* Wd = (const float*)d_in[3];
    const float* A  = (const float*)d_in[4];
    const float* dp = (const float*)d_in[5];

    ssm_proj_kernel<<<NBLK_PROJ, TPB>>>(x, Wb, Wc, Wd);
    ssm_expand_kernel<<<NBLK_EXP, TPB>>>(x, A, dp, (float*)d_out);
}